// round 8
// baseline (speedup 1.0000x reference)
#include <cuda_runtime.h>
#include <stdint.h>

#define IN_SIZE  4096
#define OUT_SIZE 4096
#define BATCH    256

#define BK      32
#define NSTAGE  (IN_SIZE / BK)     // 128
#define STAGES  4
#define A_BYTES 8192               // 64 rows x 128B
#define B_BYTES 16384              // 128 rows x 128B
#define STAGE_BYTES (A_BYTES + B_BYTES)
#define SMEM_BYTES (STAGES * STAGE_BYTES)

// Transposed dense weight g_Wt[out][in]; entries are tf32-rounded values.
__device__ float    g_Wt[(size_t)IN_SIZE * OUT_SIZE];
__device__ uint32_t g_Xt[(size_t)BATCH * IN_SIZE];     // X as tf32 (RNA) bits
__device__ int      g_idx_is64;

// ---------------------------------------------------------------------------
// helpers
// ---------------------------------------------------------------------------
__device__ __forceinline__ uint32_t f2tf32(float f) {
    uint32_t u;
    asm("cvt.rna.tf32.f32 %0, %1;" : "=r"(u) : "f"(f));
    return u;
}
__device__ __forceinline__ uint32_t smem_u32(const void* p) {
    uint32_t a;
    asm("{ .reg .u64 t; cvta.to.shared.u64 t, %1; cvt.u32.u64 %0, t; }"
        : "=r"(a) : "l"(p));
    return a;
}
__device__ __forceinline__ void cpa16(uint32_t s, const void* g) {
    asm volatile("cp.async.cg.shared.global [%0], [%1], 16;" :: "r"(s), "l"(g));
}
__device__ __forceinline__ void cpa_commit() {
    asm volatile("cp.async.commit_group;" ::: "memory");
}
template <int N>
__device__ __forceinline__ void cpa_wait() {
    asm volatile("cp.async.wait_group %0;" :: "n"(N) : "memory");
}
__device__ __forceinline__ void ldsm_x4(uint32_t& r0, uint32_t& r1,
                                        uint32_t& r2, uint32_t& r3, uint32_t a) {
    asm volatile("ldmatrix.sync.aligned.m8n8.x4.shared.b16 {%0,%1,%2,%3}, [%4];"
                 : "=r"(r0), "=r"(r1), "=r"(r2), "=r"(r3) : "r"(a));
}
__device__ __forceinline__ void mma_tf32(float& d0, float& d1, float& d2, float& d3,
                                         uint32_t a0, uint32_t a1, uint32_t a2, uint32_t a3,
                                         uint32_t b0, uint32_t b1) {
    asm volatile(
        "mma.sync.aligned.m16n8k8.row.col.f32.tf32.tf32.f32 "
        "{%0,%1,%2,%3}, {%4,%5,%6,%7}, {%8,%9}, {%0,%1,%2,%3};"
        : "+f"(d0), "+f"(d1), "+f"(d2), "+f"(d3)
        : "r"(a0), "r"(a1), "r"(a2), "r"(a3), "r"(b0), "r"(b1));
}

// ---------------------------------------------------------------------------
// Zero Wt + fused idx dtype detection (block 0).
// ---------------------------------------------------------------------------
__global__ void zero_w_detect_kernel(const uint32_t* __restrict__ idx_words) {
    size_t i = (size_t)blockIdx.x * blockDim.x + threadIdx.x;
    reinterpret_cast<float4*>(g_Wt)[i] = make_float4(0.f, 0.f, 0.f, 0.f);
    if (blockIdx.x == 0 && threadIdx.x == 0) {
        uint32_t acc = 0;
#pragma unroll
        for (int j = 0; j < 64; ++j) acc |= idx_words[2 * j + 1];
        g_idx_is64 = (acc == 0u) ? 1 : 0;
    }
}

// ---------------------------------------------------------------------------
// Scatter: g_Wt[col][row] += tf32(val). 4 entries per thread, vector loads.
// ---------------------------------------------------------------------------
__global__ void scatter_kernel(const void* __restrict__ idx,
                               const float* __restrict__ val,
                               int nnz) {
    const int base = (blockIdx.x * blockDim.x + threadIdx.x) * 4;
    if (base >= nnz) return;
    const int is64 = g_idx_is64;

    if (base + 4 <= nnz) {
        float4 v4 = *reinterpret_cast<const float4*>(val + base);
        float v[4] = {v4.x, v4.y, v4.z, v4.w};
        int row[4], col[4];
        if (is64) {
            const longlong2* p = reinterpret_cast<const longlong2*>(idx) + base;
            longlong2 e0 = p[0], e1 = p[1], e2 = p[2], e3 = p[3];
            row[0] = (int)e0.x; col[0] = (int)e0.y;
            row[1] = (int)e1.x; col[1] = (int)e1.y;
            row[2] = (int)e2.x; col[2] = (int)e2.y;
            row[3] = (int)e3.x; col[3] = (int)e3.y;
        } else {
            const int4* p = reinterpret_cast<const int4*>(idx) + base / 2;
            int4 e0 = p[0], e1 = p[1];
            row[0] = e0.x; col[0] = e0.y;
            row[1] = e0.z; col[1] = e0.w;
            row[2] = e1.x; col[2] = e1.y;
            row[3] = e1.z; col[3] = e1.w;
        }
#pragma unroll
        for (int j = 0; j < 4; ++j) {
            float w = __uint_as_float(f2tf32(v[j]));
            atomicAdd(&g_Wt[(size_t)col[j] * IN_SIZE + row[j]], w);
        }
    } else {
        for (int i = base; i < nnz; ++i) {
            int row, col;
            if (is64) {
                longlong2 p = reinterpret_cast<const longlong2*>(idx)[i];
                row = (int)p.x; col = (int)p.y;
            } else {
                int2 p = reinterpret_cast<const int2*>(idx)[i];
                row = p.x; col = p.y;
            }
            float w = __uint_as_float(f2tf32(val[i]));
            atomicAdd(&g_Wt[(size_t)col * IN_SIZE + row], w);
        }
    }
}

// ---------------------------------------------------------------------------
// X -> tf32 bits (RNA)
// ---------------------------------------------------------------------------
__global__ void cvt_x_kernel(const float* __restrict__ X) {
    size_t i = (size_t)blockIdx.x * blockDim.x + threadIdx.x;
    float4 v = reinterpret_cast<const float4*>(X)[i];
    uint4 u = make_uint4(f2tf32(v.x), f2tf32(v.y), f2tf32(v.z), f2tf32(v.w));
    reinterpret_cast<uint4*>(g_Xt)[i] = u;
}

// ---------------------------------------------------------------------------
// tf32 mma.sync GEMM v6 (in-CTA split-K): out = relu(X @ Wt^T + bias)
//
// CTA 64(M) x 128(N), 256 threads = 8 warps, 2 k-groups of 4 warps.
// k-group g handles ks = {2g, 2g+1} of each 32-wide stage; warp tile 32x64
// (warpm = wid&1, warpn = (wid>>1)&1), private accumulators.
// End: kgroup 1 stores partials to smem ([q][thread] conflict-free layout),
// kgroup 0 adds and runs the bias+relu epilogue.
// 2 warps/SMSP doubles latency hiding vs v5; crossbar bytes/stage unchanged.
// ---------------------------------------------------------------------------
__global__ __launch_bounds__(256, 1)
void gemm_tf32_mma(const float* __restrict__ bias, float* __restrict__ out) {
    extern __shared__ uint32_t smu[];
    const uint32_t sbase0 = smem_u32(smu);

    const int tid   = threadIdx.x;
    const int lane  = tid & 31;
    const int wid   = tid >> 5;
    const int kg    = wid >> 2;         // 0..1 k-group
    const int warpm = wid & 1;          // 0..1 -> 32 rows
    const int warpn = (wid >> 1) & 1;   // 0..1 -> 64 cols
    const int m0 = blockIdx.y * 64;
    const int n0 = blockIdx.x * 128;

    // staging: srow 0..31, sj 0..7; A rows srow+32i (i<2), B rows srow+32i (i<4)
    const int srow = tid >> 3;
    const int sj   = tid & 7;

    const uint32_t* Ag = g_Xt + (size_t)(m0 + srow) * IN_SIZE + sj * 4;
    const uint32_t* Bg = reinterpret_cast<const uint32_t*>(g_Wt) +
                         (size_t)(n0 + srow) * IN_SIZE + sj * 4;

    const uint32_t swz = (uint32_t)((sj ^ (srow & 7)) << 4);
    uint32_t offA[2], offB[4];
#pragma unroll
    for (int i = 0; i < 2; ++i)
        offA[i] = (uint32_t)((srow + 32 * i) * 128) + swz;
#pragma unroll
    for (int i = 0; i < 4; ++i)
        offB[i] = A_BYTES + (uint32_t)((srow + 32 * i) * 128) + swz;

    // ldmatrix lane-address components
    const int l7 = lane & 7;
    const int qa = lane >> 4;            // A k-quad select (mats 2,3)
    const int qb = (lane >> 3) & 1;      // B k-quad select
    uint32_t rAbase[2];
#pragma unroll
    for (int msub = 0; msub < 2; ++msub)
        rAbase[msub] = (uint32_t)((warpm * 32 + msub * 16 +
                                   ((lane >> 3) & 1) * 8 + l7) * 128);
    uint32_t rBbase[4];
#pragma unroll
    for (int p = 0; p < 4; ++p)
        rBbase[p] = (uint32_t)((warpn * 64 + p * 16 + ((lane >> 4) << 3) + l7) * 128);

    float acc[2][8][4];
#pragma unroll
    for (int a = 0; a < 2; ++a)
#pragma unroll
        for (int b = 0; b < 8; ++b)
#pragma unroll
            for (int d = 0; d < 4; ++d) acc[a][b][d] = 0.f;

    // ---- prologue: issue stages 0..2
#pragma unroll
    for (int ps = 0; ps < 3; ++ps) {
        const uint32_t sb = sbase0 + (uint32_t)ps * STAGE_BYTES;
#pragma unroll
        for (int i = 0; i < 2; ++i)
            cpa16(sb + offA[i], Ag + (size_t)(32 * i) * IN_SIZE + ps * BK);
#pragma unroll
        for (int i = 0; i < 4; ++i)
            cpa16(sb + offB[i], Bg + (size_t)(32 * i) * IN_SIZE + ps * BK);
        cpa_commit();
    }

    for (int s = 0; s < NSTAGE; ++s) {
        cpa_wait<2>();
        __syncthreads();   // stage s visible AND stage s-1 compute done

        if (s + 3 < NSTAGE) {
            const uint32_t nb = sbase0 + (uint32_t)((s + 3) & 3) * STAGE_BYTES;
            const int ko = (s + 3) * BK;
#pragma unroll
            for (int i = 0; i < 2; ++i)
                cpa16(nb + offA[i], Ag + (size_t)(32 * i) * IN_SIZE + ko);
#pragma unroll
            for (int i = 0; i < 4; ++i)
                cpa16(nb + offB[i], Bg + (size_t)(32 * i) * IN_SIZE + ko);
        }
        cpa_commit();

        const uint32_t sb = sbase0 + (uint32_t)(s & 3) * STAGE_BYTES;
#pragma unroll
        for (int ksl = 0; ksl < 2; ++ksl) {
            const int ks = kg * 2 + ksl;
            const uint32_t aswz = (uint32_t)(((ks * 2 + qa) ^ l7) << 4);
            const uint32_t bswz = (uint32_t)(((ks * 2 + qb) ^ l7) << 4);
            uint32_t af[2][4];
#pragma unroll
            for (int msub = 0; msub < 2; ++msub)
                ldsm_x4(af[msub][0], af[msub][1], af[msub][2], af[msub][3],
                        sb + rAbase[msub] + aswz);
            uint32_t bf[8][2];
#pragma unroll
            for (int p = 0; p < 4; ++p)
                ldsm_x4(bf[2 * p][0], bf[2 * p][1], bf[2 * p + 1][0], bf[2 * p + 1][1],
                        sb + A_BYTES + rBbase[p] + bswz);
#pragma unroll
            for (int msub = 0; msub < 2; ++msub)
#pragma unroll
                for (int nsub = 0; nsub < 8; ++nsub)
                    mma_tf32(acc[msub][nsub][0], acc[msub][nsub][1],
                             acc[msub][nsub][2], acc[msub][nsub][3],
                             af[msub][0], af[msub][1], af[msub][2], af[msub][3],
                             bf[nsub][0], bf[nsub][1]);
        }
    }

    // ---- split-K reduction: kgroup 1 -> smem, kgroup 0 adds
    __syncthreads();   // all compute done; safe to reuse stage buffers
    const int tlocal = (wid & 3) * 32 + lane;   // 0..127 within k-group
    if (kg == 1) {
#pragma unroll
        for (int q = 0; q < 16; ++q) {
            const int msub = q >> 3, nsub = q & 7;
            float4 v = make_float4(acc[msub][nsub][0], acc[msub][nsub][1],
                                   acc[msub][nsub][2], acc[msub][nsub][3]);
            *reinterpret_cast<float4*>((char*)smu + (size_t)(q * 128 + tlocal) * 16) = v;
        }
    }
    __syncthreads();
    if (kg == 0) {
#pragma unroll
        for (int q = 0; q < 16; ++q) {
            const int msub = q >> 3, nsub = q & 7;
            float4 v = *reinterpret_cast<const float4*>(
                (char*)smu + (size_t)(q * 128 + tlocal) * 16);
            acc[msub][nsub][0] += v.x;
            acc[msub][nsub][1] += v.y;
            acc[msub][nsub][2] += v.z;
            acc[msub][nsub][3] += v.w;
        }

        // ---- epilogue: bias + relu, float2 stores
#pragma unroll
        for (int msub = 0; msub < 2; ++msub) {
            const int m = m0 + warpm * 32 + msub * 16 + (lane >> 2);
#pragma unroll
            for (int nsub = 0; nsub < 8; ++nsub) {
                const int n = n0 + warpn * 64 + nsub * 8 + (lane & 3) * 2;
                float2 bv = *reinterpret_cast<const float2*>(bias + n);
                float2 o0, o1;
                o0.x = fmaxf(acc[msub][nsub][0] + bv.x, 0.f);
                o0.y = fmaxf(acc[msub][nsub][1] + bv.y, 0.f);
                o1.x = fmaxf(acc[msub][nsub][2] + bv.x, 0.f);
                o1.y = fmaxf(acc[msub][nsub][3] + bv.y, 0.f);
                *reinterpret_cast<float2*>(out + (size_t)m * OUT_SIZE + n)       = o0;
                *reinterpret_cast<float2*>(out + (size_t)(m + 8) * OUT_SIZE + n) = o1;
            }
        }
    }
}

// ---------------------------------------------------------------------------
// kernel_launch
// ---------------------------------------------------------------------------
extern "C" void kernel_launch(void* const* d_in, const int* in_sizes, int n_in,
                              void* d_out, int out_size) {
    const float* X    = (const float*)d_in[0];
    const void*  idx  = d_in[1];
    const float* val  = (const float*)d_in[2];
    const float* bias = (const float*)d_in[3];
    float*       out  = (float*)d_out;

    const int nnz = in_sizes[2];

    zero_w_detect_kernel<<<(int)(((size_t)IN_SIZE * OUT_SIZE / 4) / 256), 256>>>(
        (const uint32_t*)idx);
    scatter_kernel<<<(nnz / 4 + 255) / 256, 256>>>(idx, val, nnz);
    cvt_x_kernel<<<(int)(((size_t)BATCH * IN_SIZE / 4) / 256), 256>>>(X);

    cudaFuncSetAttribute(gemm_tf32_mma,
                         cudaFuncAttributeMaxDynamicSharedMemorySize, SMEM_BYTES);
    dim3 grid(OUT_SIZE / 128, BATCH / 64);   // (32, 4) = 128 CTAs
    gemm_tf32_mma<<<grid, 256, SMEM_BYTES>>>(bias, out);
}